// round 12
// baseline (speedup 1.0000x reference)
#include <cuda_runtime.h>
#include <math.h>

#define EPSF 1e-5f

typedef unsigned long long u64;
typedef unsigned int u32;

__device__ __forceinline__ u64 pk2(float a, float b) {
    u64 r;
    asm("mov.b64 %0, {%1, %2};" : "=l"(r) : "r"(__float_as_uint(a)), "r"(__float_as_uint(b)));
    return r;
}
__device__ __forceinline__ u64 ffma2(u64 a, u64 b, u64 c) {
    u64 d;
    asm("fma.rn.f32x2 %0, %1, %2, %3;" : "=l"(d) : "l"(a), "l"(b), "l"(c));
    return d;
}
__device__ __forceinline__ void upk2(u64 v, float& lo, float& hi) {
    unsigned int l, h;
    asm("mov.b64 {%0, %1}, %2;" : "=r"(l), "=r"(h) : "l"(v));
    lo = __uint_as_float(l); hi = __uint_as_float(h);
}
__device__ __forceinline__ float gelu_f(float v) {
    return 0.5f * v * (1.0f + erff(v * 0.70710678118654752f));
}
__device__ __forceinline__ u32 tf32c(float f) {
    u32 r;
    asm("cvt.rna.tf32.f32 %0, %1;" : "=r"(r) : "f"(f));
    return r;
}

/* intermediates */
__device__ float g_x1[4 * 64 * 9216];    /* gelu(bn(involution)) */
__device__ float g_kern[196 * 36864];    /* per-pixel kernels [g*49+o][pix] */

/* ====== K01: x -> t (in smem) -> kern[196][pix]  (fused reduce+span) ====== */
#define J_XS    0        /* [c=64][px=64] = 4096 */
#define J_WR    4096     /* [c][16] folded = 1024 */
#define J_BR    5120     /* 16 */
#define J_TPART 5136     /* [4][64][18] = 4608 */
#define J_T     9744     /* [px=64][18] = 1152 */
#define J_WSP   10896    /* u64 [g][25][16] = 1600 u64 = 3200 floats */
#define J_BSP   14096    /* u64 [g][25] = 100 u64 = 200 floats */
#define J_FLOATS 14296
#define J_BYTES (J_FLOATS * 4)   /* 57184 B -> 3 CTAs/SM */

__global__ void __launch_bounds__(256, 3)
k01_kern(const float* __restrict__ x,
         const float* __restrict__ w_reduce,
         const float* __restrict__ g_r, const float* __restrict__ b_r,
         const float* __restrict__ m_r, const float* __restrict__ v_r,
         const float* __restrict__ w_span, const float* __restrict__ b_span)
{
    extern __shared__ float sm[];
    u64* wsp = (u64*)(sm + J_WSP);
    u64* bsp = (u64*)(sm + J_BSP);
    const int tid = threadIdx.x;

    const int pix0 = blockIdx.x * 64;
    const int b    = pix0 / 9216;
    const int hw0  = pix0 - b * 9216;

    {
        const float* xb = x + b * 64 * 9216 + hw0;
#pragma unroll
        for (int j = 0; j < 16; j++) {
            int i = tid + j * 256;
            int c = i >> 6, p = i & 63;
            sm[J_XS + i] = xb[c * 9216 + p];
        }
    }
    for (int i = tid; i < 1024; i += 256) {
        int c = i >> 4, r = i & 15;
        float sc = g_r[r] * rsqrtf(v_r[r] + EPSF);
        sm[J_WR + c * 16 + r] = w_reduce[r * 64 + c] * sc;
    }
    if (tid < 16) {
        float sc = g_r[tid] * rsqrtf(v_r[tid] + EPSF);
        sm[J_BR + tid] = b_r[tid] - m_r[tid] * sc;
    }
    for (int i = tid; i < 1600; i += 256) {
        int g = i / 400, rem = i - g * 400;
        int op = rem >> 4, r = rem & 15;
        float lo = w_span[(g * 49 + 2 * op) * 16 + r];
        float hi = (2 * op + 1 < 49) ? w_span[(g * 49 + 2 * op + 1) * 16 + r] : 0.f;
        wsp[i] = pk2(lo, hi);
    }
    if (tid < 100) {
        int g = tid / 25, op = tid - g * 25;
        float lo = b_span[g * 49 + 2 * op];
        float hi = (2 * op + 1 < 49) ? b_span[g * 49 + 2 * op + 1] : 0.f;
        bsp[tid] = pk2(lo, hi);
    }
    __syncthreads();

    const int px = tid & 63;
    const int cq = tid >> 6;

    {
        u64 t2[8];
#pragma unroll
        for (int q = 0; q < 8; q++) t2[q] = 0ULL;
#pragma unroll
        for (int c = 0; c < 16; c++) {
            float xv = sm[J_XS + (cq * 16 + c) * 64 + px];
            u64 xv2 = pk2(xv, xv);
            const ulonglong2* w2 = (const ulonglong2*)(sm + J_WR + (cq * 16 + c) * 16);
#pragma unroll
            for (int q = 0; q < 4; q++) {
                ulonglong2 w = w2[q];
                t2[2 * q + 0] = ffma2(w.x, xv2, t2[2 * q + 0]);
                t2[2 * q + 1] = ffma2(w.y, xv2, t2[2 * q + 1]);
            }
        }
        float* pb = sm + J_TPART + (cq * 64 + px) * 18;
#pragma unroll
        for (int q = 0; q < 8; q++) upk2(t2[q], pb[2 * q], pb[2 * q + 1]);
    }
    __syncthreads();

#pragma unroll
    for (int j = 0; j < 4; j++) {
        int r = cq * 4 + j;
        float s = sm[J_TPART + (0 * 64 + px) * 18 + r]
                + sm[J_TPART + (1 * 64 + px) * 18 + r]
                + sm[J_TPART + (2 * 64 + px) * 18 + r]
                + sm[J_TPART + (3 * 64 + px) * 18 + r];
        s += sm[J_BR + r];
        sm[J_T + px * 18 + r] = fmaxf(s, 0.f);
    }
    __syncthreads();

    const int g = cq;
    u64 t2[16];
    {
        const float* tp = sm + J_T + px * 18;
#pragma unroll
        for (int r = 0; r < 16; r++) { float v = tp[r]; t2[r] = pk2(v, v); }
    }

    float* kout = g_kern + g * 49 * 36864 + pix0 + px;
#pragma unroll 4
    for (int op = 0; op < 25; op++) {
        u64 a = bsp[g * 25 + op];
        const ulonglong2* w2 = (const ulonglong2*)(wsp + (g * 25 + op) * 16);
#pragma unroll
        for (int q = 0; q < 8; q++) {
            ulonglong2 w = w2[q];
            a = ffma2(w.x, t2[2 * q],     a);
            a = ffma2(w.y, t2[2 * q + 1], a);
        }
        float e0, e1; upk2(a, e0, e1);
        kout[(2 * op) * 36864] = e0;
        if (op < 24) kout[(2 * op + 1) * 36864] = e1;
    }
}

/* ============ K1b: involution + BN + gelu (channel-pair f32x2) ============ */
#define B1W 16
#define B1H 4
#define P2W 22
#define P2H 10
#define P2PIX (P2W * P2H)    /* 220 */

#define B_X2  0              /* [cp=32][220] float2 = 14080 floats */
#define B_SI  14080
#define B_SHI 14144
#define B_FLOATS 14208
#define B_BYTES (B_FLOATS * 4)   /* 56832 -> 3 CTAs/SM */

__global__ void __launch_bounds__(256, 3)
k1b_involution(const float* __restrict__ x,
               const float* __restrict__ g_i, const float* __restrict__ b_i,
               const float* __restrict__ m_i, const float* __restrict__ v_i)
{
    extern __shared__ float sm[];
    const int tid = threadIdx.x;
    const int bb  = blockIdx.z;
    const int h0  = blockIdx.y * B1H;
    const int w0  = blockIdx.x * B1W;

    {
        const int xbase = bb * 64 * 9216;
        float2* x2 = (float2*)(sm + B_X2);
        for (int i = tid; i < 32 * P2PIX; i += 256) {
            int cp = i / P2PIX;
            int p  = i - cp * P2PIX;
            int r  = p / P2W;
            int cl = p - r * P2W;
            int gh = h0 + r - 3;
            int gw = w0 + cl - 3;
            float v0 = 0.f, v1 = 0.f;
            if ((unsigned)gh < 96u && (unsigned)gw < 96u) {
                int a = xbase + (2 * cp) * 9216 + gh * 96 + gw;
                v0 = x[a];
                v1 = x[a + 9216];
            }
            x2[i] = make_float2(v0, v1);
        }
    }
    if (tid < 64) {
        float sc = g_i[tid] * rsqrtf(v_i[tid] + EPSF);
        sm[B_SI + tid]  = sc;
        sm[B_SHI + tid] = b_i[tid] - m_i[tid] * sc;
    }
    __syncthreads();

    const int px = tid & 63;
    const int g  = tid >> 6;
    const int lx = px & 15;
    const int ly = px >> 4;
    const int hw = (h0 + ly) * 96 + (w0 + lx);
    const int pixg = bb * 9216 + hw;

    float kr[49];
    {
        const float* kp = g_kern + g * 49 * 36864 + pixg;
#pragma unroll
        for (int kk = 0; kk < 49; kk++) kr[kk] = kp[kk * 36864];
    }

    u64 acc2[8];
#pragma unroll
    for (int q = 0; q < 8; q++) acc2[q] = 0ULL;

    const u64* xt = (const u64*)(sm + B_X2);
#pragma unroll
    for (int i = 0; i < 7; i++) {
        u64 kd[7];
#pragma unroll
        for (int j = 0; j < 7; j++) kd[j] = pk2(kr[i * 7 + j], kr[i * 7 + j]);
        const int rowoff = (ly + i) * P2W + lx;
#pragma unroll
        for (int cp8 = 0; cp8 < 8; cp8++) {
            const u64* xb = xt + (g * 8 + cp8) * P2PIX + rowoff;
            u64 a = acc2[cp8];
            a = ffma2(kd[0], xb[0], a);
            a = ffma2(kd[1], xb[1], a);
            a = ffma2(kd[2], xb[2], a);
            a = ffma2(kd[3], xb[3], a);
            a = ffma2(kd[4], xb[4], a);
            a = ffma2(kd[5], xb[5], a);
            a = ffma2(kd[6], xb[6], a);
            acc2[cp8] = a;
        }
    }

    float* ob = g_x1 + bb * 64 * 9216 + hw;
#pragma unroll
    for (int cp8 = 0; cp8 < 8; cp8++) {
        float lo, hi; upk2(acc2[cp8], lo, hi);
        int c0 = g * 16 + 2 * cp8;
        float v0 = fmaf(lo, sm[B_SI + c0],     sm[B_SHI + c0]);
        float v1 = fmaf(hi, sm[B_SI + c0 + 1], sm[B_SHI + c0 + 1]);
        ob[c0 * 9216]       = gelu_f(v0);
        ob[(c0 + 1) * 9216] = gelu_f(v1);
    }
}

/* ======= K2: tf32 MMA GEMM, B in swizzled SMEM (LDS.128 fragments) ======= */
/* Y layout per k-row: element for pixel px lives at (px&7)*16 + (px>>3).
   Thread (gid,tig) then reads its 16 nt-values contiguously.              */
#define S2_W    0            /* u32 128*132 = 16896 */
#define S2_CST  16896        /* 128 */
#define S2_Y    17024        /* [2][16][128] = 4096 */
#define S2_FLOATS 21120
#define S2_BYTES (S2_FLOATS * 4)   /* 84480 -> 2 CTAs/SM */

__global__ void __launch_bounds__(256, 2)
k2_mma(const float* __restrict__ x,
       const float* __restrict__ w_conv,
       const float* __restrict__ g_c, const float* __restrict__ b_c,
       const float* __restrict__ m_c, const float* __restrict__ v_c,
       const float* __restrict__ w_map, const float* __restrict__ b_map,
       const float* __restrict__ g_m, const float* __restrict__ b_m,
       const float* __restrict__ m_m, const float* __restrict__ v_m,
       float* __restrict__ out)
{
    extern __shared__ float smf[];
    u32* smu = (u32*)smf;
    const int tid = threadIdx.x;

    for (int i = tid; i < 16384; i += 256) {
        int o = i >> 7, k = i & 127;
        float v;
        if (k < 64) v = w_conv[o * 64 + k]        * (g_c[o] * rsqrtf(v_c[o] + EPSF));
        else        v = w_map [o * 64 + (k - 64)] * (g_m[o] * rsqrtf(v_m[o] + EPSF));
        smu[S2_W + o * 132 + k] = tf32c(v);
    }
    if (tid < 128) {
        float sc_c = g_c[tid] * rsqrtf(v_c[tid] + EPSF);
        float sc_m = g_m[tid] * rsqrtf(v_m[tid] + EPSF);
        smf[S2_CST + tid] = (b_c[tid] - m_c[tid] * sc_c)
                          + sc_m * b_map[tid]
                          + (b_m[tid] - m_m[tid] * sc_m);
    }

    const int P0  = blockIdx.x * 128;
    const int b   = P0 / 9216;
    const int off = P0 - b * 9216;

    const int ldr = tid >> 4;            /* k row 0..15 */
    const int ldc8 = tid & 15;           /* px block: px = ldc8*8 + j */
    const float* x1base = g_x1 + (b * 64) * 9216 + off;
    const float* xbase  = x    + (b * 64) * 9216 + off;

    /* stage chunk 0: write swizzled — value j goes to [j*16 + ldc8] */
    float4 v0 = *(const float4*)(x1base + ldr * 9216 + ldc8 * 8);
    float4 v1 = *(const float4*)(x1base + ldr * 9216 + ldc8 * 8 + 4);
    {
        u32* yd = smu + S2_Y + ldr * 128 + ldc8;
        yd[0 * 16] = tf32c(v0.x); yd[1 * 16] = tf32c(v0.y);
        yd[2 * 16] = tf32c(v0.z); yd[3 * 16] = tf32c(v0.w);
        yd[4 * 16] = tf32c(v1.x); yd[5 * 16] = tf32c(v1.y);
        yd[6 * 16] = tf32c(v1.z); yd[7 * 16] = tf32c(v1.w);
    }
    __syncthreads();

    const int lane = tid & 31;
    const int gid  = lane >> 2;
    const int tig  = lane & 3;
    const int m0   = (tid >> 5) * 16;

    float c[16][4];
#pragma unroll
    for (int nt = 0; nt < 16; nt++)
#pragma unroll
        for (int q = 0; q < 4; q++) c[nt][q] = 0.f;

#pragma unroll 1
    for (int ch = 0; ch < 8; ch++) {
        if (ch < 7) {
            int kg = (ch + 1) * 16 + ldr;
            const float* src = (kg < 64) ? (x1base + kg * 9216)
                                         : (xbase + (kg - 64) * 9216);
            v0 = *(const float4*)(src + ldc8 * 8);
            v1 = *(const float4*)(src + ldc8 * 8 + 4);
        }

        const u32* Yb = smu + S2_Y + (ch & 1) * 2048;
#pragma unroll
        for (int ks = 0; ks < 2; ks++) {
            const int kg = ch * 16 + ks * 8;
            u32 a0 = smu[S2_W + (m0 + gid) * 132 + kg + tig];
            u32 a2 = smu[S2_W + (m0 + gid) * 132 + kg + tig + 4];
            u32 a1 = smu[S2_W + (m0 + gid + 8) * 132 + kg + tig];
            u32 a3 = smu[S2_W + (m0 + gid + 8) * 132 + kg + tig + 4];
            const uint4* p0 = (const uint4*)(Yb + (ks * 8 + tig) * 128 + gid * 16);
            const uint4* p1 = (const uint4*)(Yb + (ks * 8 + tig + 4) * 128 + gid * 16);
#pragma unroll
            for (int q = 0; q < 4; q++) {
                uint4 bq0 = p0[q];
                uint4 bq1 = p1[q];
                asm volatile(
                    "mma.sync.aligned.m16n8k8.row.col.f32.tf32.tf32.f32 "
                    "{%0,%1,%2,%3}, {%4,%5,%6,%7}, {%8,%9}, {%0,%1,%2,%3};"
                    : "+f"(c[4*q+0][0]), "+f"(c[4*q+0][1]), "+f"(c[4*q+0][2]), "+f"(c[4*q+0][3])
                    : "r"(a0), "r"(a1), "r"(a2), "r"(a3), "r"(bq0.x), "r"(bq1.x));
                asm volatile(
                    "mma.sync.aligned.m16n8k8.row.col.f32.tf32.tf32.f32 "
                    "{%0,%1,%2,%3}, {%4,%5,%6,%7}, {%8,%9}, {%0,%1,%2,%3};"
                    : "+f"(c[4*q+1][0]), "+f"(c[4*q+1][1]), "+f"(c[4*q+1][2]), "+f"(c[4*q+1][3])
                    : "r"(a0), "r"(a1), "r"(a2), "r"(a3), "r"(bq0.y), "r"(bq1.y));
                asm volatile(
                    "mma.sync.aligned.m16n8k8.row.col.f32.tf32.tf32.f32 "
                    "{%0,%1,%2,%3}, {%4,%5,%6,%7}, {%8,%9}, {%0,%1,%2,%3};"
                    : "+f"(c[4*q+2][0]), "+f"(c[4*q+2][1]), "+f"(c[4*q+2][2]), "+f"(c[4*q+2][3])
                    : "r"(a0), "r"(a1), "r"(a2), "r"(a3), "r"(bq0.z), "r"(bq1.z));
                asm volatile(
                    "mma.sync.aligned.m16n8k8.row.col.f32.tf32.tf32.f32 "
                    "{%0,%1,%2,%3}, {%4,%5,%6,%7}, {%8,%9}, {%0,%1,%2,%3};"
                    : "+f"(c[4*q+3][0]), "+f"(c[4*q+3][1]), "+f"(c[4*q+3][2]), "+f"(c[4*q+3][3])
                    : "r"(a0), "r"(a1), "r"(a2), "r"(a3), "r"(bq0.w), "r"(bq1.w));
            }
        }

        if (ch < 7) {
            u32* yd = smu + S2_Y + ((ch + 1) & 1) * 2048 + ldr * 128 + ldc8;
            yd[0 * 16] = tf32c(v0.x); yd[1 * 16] = tf32c(v0.y);
            yd[2 * 16] = tf32c(v0.z); yd[3 * 16] = tf32c(v0.w);
            yd[4 * 16] = tf32c(v1.x); yd[5 * 16] = tf32c(v1.y);
            yd[6 * 16] = tf32c(v1.z); yd[7 * 16] = tf32c(v1.w);
        }
        __syncthreads();
    }

    /* epilogue: nt maps to px = nt*8 + gid... careful: with swizzle, col n of
       the mma (= gid per b-fragment col) — fragment col index within n8 tile
       is gid; tile q*4+j covers px whose (px>>3)==nt, (px&7)==col.
       So px = nt*8 ... wait: Y[k][(px&7)*16 + (px>>3)]: fragment for tile nt
       used b at offset gid*16 + nt -> (px&7)=gid, (px>>3)=nt -> px = nt*8+gid.
       But mma n-index within tile: col = gid? mma b fragment: thread (gid,tig)
       supplies b[row=tig(+4)][col=gid]; c fragment: thread holds c[row gid(+8)]
       [cols 2*tig, 2*tig+1]. So output cols of tile nt are px = nt*8 + colidx,
       colidx = 2*tig, 2*tig+1. */
    float* ob = out + (b * 128) * 9216 + off;
    const int o0 = m0 + gid;
    const float cst0 = smf[S2_CST + o0];
    const float cst1 = smf[S2_CST + o0 + 8];
#pragma unroll
    for (int nt = 0; nt < 16; nt++) {
        int pxl = nt * 8 + tig * 2;
        float2 r0, r1;
        r0.x = gelu_f(c[nt][0] + cst0);
        r0.y = gelu_f(c[nt][1] + cst0);
        r1.x = gelu_f(c[nt][2] + cst1);
        r1.y = gelu_f(c[nt][3] + cst1);
        *(float2*)(ob + o0 * 9216 + pxl)       = r0;
        *(float2*)(ob + (o0 + 8) * 9216 + pxl) = r1;
    }
}

extern "C" void kernel_launch(void* const* d_in, const int* in_sizes, int n_in,
                              void* d_out, int out_size)
{
    (void)in_sizes; (void)n_in; (void)out_size;
    const float* x        = (const float*)d_in[0];
    const float* w_reduce = (const float*)d_in[1];
    const float* g_r = (const float*)d_in[2];
    const float* b_r = (const float*)d_in[3];
    const float* m_r = (const float*)d_in[4];
    const float* v_r = (const float*)d_in[5];
    const float* w_span = (const float*)d_in[6];
    const float* b_span = (const float*)d_in[7];
    const float* g_i = (const float*)d_in[8];
    const float* b_i = (const float*)d_in[9];
    const float* m_i = (const float*)d_in[10];
    const float* v_i = (const float*)d_in[11];
    const float* w_conv = (const float*)d_in[12];
    const float* g_c = (const float*)d_in[13];
    const float* b_c = (const float*)d_in[14];
    const float* m_c = (const float*)d_in[15];
    const float* v_c = (const float*)d_in[16];
    const float* w_map = (const float*)d_in[17];
    const float* b_map = (const float*)d_in[18];
    const float* g_m = (const float*)d_in[19];
    const float* b_m = (const float*)d_in[20];
    const float* m_m = (const float*)d_in[21];
    const float* v_m = (const float*)d_in[22];
    float* out = (float*)d_out;

    cudaFuncSetAttribute(k01_kern,       cudaFuncAttributeMaxDynamicSharedMemorySize, J_BYTES);
    cudaFuncSetAttribute(k1b_involution, cudaFuncAttributeMaxDynamicSharedMemorySize, B_BYTES);
    cudaFuncSetAttribute(k2_mma,         cudaFuncAttributeMaxDynamicSharedMemorySize, S2_BYTES);

    k01_kern<<<576, 256, J_BYTES>>>(x, w_reduce, g_r, b_r, m_r, v_r, w_span, b_span);

    dim3 gb(96 / B1W, 96 / B1H, 4);
    k1b_involution<<<gb, 256, B_BYTES>>>(x, g_i, b_i, m_i, v_i);

    k2_mma<<<288, 256, S2_BYTES>>>(x, w_conv, g_c, b_c, m_c, v_c,
                                   w_map, b_map, g_m, b_m, m_m, v_m, out);
}

// round 13
// speedup vs baseline: 1.0363x; 1.0363x over previous
#include <cuda_runtime.h>
#include <math.h>

#define EPSF 1e-5f

typedef unsigned long long u64;
typedef unsigned int u32;

__device__ __forceinline__ u64 pk2(float a, float b) {
    u64 r;
    asm("mov.b64 %0, {%1, %2};" : "=l"(r) : "r"(__float_as_uint(a)), "r"(__float_as_uint(b)));
    return r;
}
__device__ __forceinline__ u64 ffma2(u64 a, u64 b, u64 c) {
    u64 d;
    asm("fma.rn.f32x2 %0, %1, %2, %3;" : "=l"(d) : "l"(a), "l"(b), "l"(c));
    return d;
}
__device__ __forceinline__ void upk2(u64 v, float& lo, float& hi) {
    unsigned int l, h;
    asm("mov.b64 {%0, %1}, %2;" : "=r"(l), "=r"(h) : "l"(v));
    lo = __uint_as_float(l); hi = __uint_as_float(h);
}
__device__ __forceinline__ float gelu_f(float v) {
    return 0.5f * v * (1.0f + erff(v * 0.70710678118654752f));
}
__device__ __forceinline__ u32 tf32c(float f) {
    u32 r;
    asm("cvt.rna.tf32.f32 %0, %1;" : "=r"(r) : "f"(f));
    return r;
}

/* intermediates */
__device__ float g_x1[4 * 64 * 9216];    /* gelu(bn(involution)) */
__device__ float g_kern[196 * 36864];    /* per-pixel kernels [g*49+o][pix] */

/* ====== K01: x -> t (direct LDG) -> kern[196][pix]  (fused reduce+span) ====== */
#define J_WR    0        /* [c][16] folded = 1024 */
#define J_BR    1024     /* 16 */
#define J_TPART 1040     /* [4][64][18] = 4608 */
#define J_T     5648     /* [px=64][18] = 1152 */
#define J_WSP   6800     /* u64 [g][25][16] = 1600 u64 = 3200 floats */
#define J_BSP   10000    /* u64 [g][25] = 100 u64 = 200 floats */
#define J_FLOATS 10200
#define J_BYTES (J_FLOATS * 4)   /* 40800 B */

__global__ void __launch_bounds__(256, 3)
k01_kern(const float* __restrict__ x,
         const float* __restrict__ w_reduce,
         const float* __restrict__ g_r, const float* __restrict__ b_r,
         const float* __restrict__ m_r, const float* __restrict__ v_r,
         const float* __restrict__ w_span, const float* __restrict__ b_span)
{
    extern __shared__ float sm[];
    u64* wsp = (u64*)(sm + J_WSP);
    u64* bsp = (u64*)(sm + J_BSP);
    const int tid = threadIdx.x;

    const int pix0 = blockIdx.x * 64;
    const int b    = pix0 / 9216;
    const int hw0  = pix0 - b * 9216;

    for (int i = tid; i < 1024; i += 256) {
        int c = i >> 4, r = i & 15;
        float sc = g_r[r] * rsqrtf(v_r[r] + EPSF);
        sm[J_WR + c * 16 + r] = w_reduce[r * 64 + c] * sc;
    }
    if (tid < 16) {
        float sc = g_r[tid] * rsqrtf(v_r[tid] + EPSF);
        sm[J_BR + tid] = b_r[tid] - m_r[tid] * sc;
    }
    for (int i = tid; i < 1600; i += 256) {
        int g = i / 400, rem = i - g * 400;
        int op = rem >> 4, r = rem & 15;
        float lo = w_span[(g * 49 + 2 * op) * 16 + r];
        float hi = (2 * op + 1 < 49) ? w_span[(g * 49 + 2 * op + 1) * 16 + r] : 0.f;
        wsp[i] = pk2(lo, hi);
    }
    if (tid < 100) {
        int g = tid / 25, op = tid - g * 25;
        float lo = b_span[g * 49 + 2 * op];
        float hi = (2 * op + 1 < 49) ? b_span[g * 49 + 2 * op + 1] : 0.f;
        bsp[tid] = pk2(lo, hi);
    }
    __syncthreads();

    const int px = tid & 63;
    const int cq = tid >> 6;

    /* t partials: quarter cq over 16 channels, x read straight from gmem */
    {
        const float* xp = x + b * 64 * 9216 + (cq * 16) * 9216 + hw0 + px;
        u64 t2[8];
#pragma unroll
        for (int q = 0; q < 8; q++) t2[q] = 0ULL;
#pragma unroll
        for (int c = 0; c < 16; c++) {
            float xv = xp[c * 9216];
            u64 xv2 = pk2(xv, xv);
            const ulonglong2* w2 = (const ulonglong2*)(sm + J_WR + (cq * 16 + c) * 16);
#pragma unroll
            for (int q = 0; q < 4; q++) {
                ulonglong2 w = w2[q];
                t2[2 * q + 0] = ffma2(w.x, xv2, t2[2 * q + 0]);
                t2[2 * q + 1] = ffma2(w.y, xv2, t2[2 * q + 1]);
            }
        }
        float* pb = sm + J_TPART + (cq * 64 + px) * 18;
#pragma unroll
        for (int q = 0; q < 8; q++) upk2(t2[q], pb[2 * q], pb[2 * q + 1]);
    }
    __syncthreads();

#pragma unroll
    for (int j = 0; j < 4; j++) {
        int r = cq * 4 + j;
        float s = sm[J_TPART + (0 * 64 + px) * 18 + r]
                + sm[J_TPART + (1 * 64 + px) * 18 + r]
                + sm[J_TPART + (2 * 64 + px) * 18 + r]
                + sm[J_TPART + (3 * 64 + px) * 18 + r];
        s += sm[J_BR + r];
        sm[J_T + px * 18 + r] = fmaxf(s, 0.f);
    }
    __syncthreads();

    const int g = cq;
    u64 t2[16];
    {
        const float* tp = sm + J_T + px * 18;
#pragma unroll
        for (int r = 0; r < 16; r++) { float v = tp[r]; t2[r] = pk2(v, v); }
    }

    float* kout = g_kern + g * 49 * 36864 + pix0 + px;
#pragma unroll 4
    for (int op = 0; op < 25; op++) {
        u64 a = bsp[g * 25 + op];
        const ulonglong2* w2 = (const ulonglong2*)(wsp + (g * 25 + op) * 16);
#pragma unroll
        for (int q = 0; q < 8; q++) {
            ulonglong2 w = w2[q];
            a = ffma2(w.x, t2[2 * q],     a);
            a = ffma2(w.y, t2[2 * q + 1], a);
        }
        float e0, e1; upk2(a, e0, e1);
        kout[(2 * op) * 36864] = e0;
        if (op < 24) kout[(2 * op + 1) * 36864] = e1;
    }
}

/* ============ K1b: involution + BN + gelu (channel-pair f32x2) ============ */
#define B1W 16
#define B1H 4
#define P2W 22
#define P2H 10
#define P2PIX (P2W * P2H)    /* 220 */

#define B_X2  0              /* [cp=32][220] float2 = 14080 floats */
#define B_SI  14080
#define B_SHI 14144
#define B_FLOATS 14208
#define B_BYTES (B_FLOATS * 4)   /* 56832 -> 3 CTAs/SM */

__global__ void __launch_bounds__(256, 3)
k1b_involution(const float* __restrict__ x,
               const float* __restrict__ g_i, const float* __restrict__ b_i,
               const float* __restrict__ m_i, const float* __restrict__ v_i)
{
    extern __shared__ float sm[];
    const int tid = threadIdx.x;
    const int bb  = blockIdx.z;
    const int h0  = blockIdx.y * B1H;
    const int w0  = blockIdx.x * B1W;

    {
        const int xbase = bb * 64 * 9216;
        float2* x2 = (float2*)(sm + B_X2);
        for (int i = tid; i < 32 * P2PIX; i += 256) {
            int cp = i / P2PIX;
            int p  = i - cp * P2PIX;
            int r  = p / P2W;
            int cl = p - r * P2W;
            int gh = h0 + r - 3;
            int gw = w0 + cl - 3;
            float v0 = 0.f, v1 = 0.f;
            if ((unsigned)gh < 96u && (unsigned)gw < 96u) {
                int a = xbase + (2 * cp) * 9216 + gh * 96 + gw;
                v0 = x[a];
                v1 = x[a + 9216];
            }
            x2[i] = make_float2(v0, v1);
        }
    }
    if (tid < 64) {
        float sc = g_i[tid] * rsqrtf(v_i[tid] + EPSF);
        sm[B_SI + tid]  = sc;
        sm[B_SHI + tid] = b_i[tid] - m_i[tid] * sc;
    }
    __syncthreads();

    const int px = tid & 63;
    const int g  = tid >> 6;
    const int lx = px & 15;
    const int ly = px >> 4;
    const int hw = (h0 + ly) * 96 + (w0 + lx);
    const int pixg = bb * 9216 + hw;

    float kr[49];
    {
        const float* kp = g_kern + g * 49 * 36864 + pixg;
#pragma unroll
        for (int kk = 0; kk < 49; kk++) kr[kk] = kp[kk * 36864];
    }

    u64 acc2[8];
#pragma unroll
    for (int q = 0; q < 8; q++) acc2[q] = 0ULL;

    const u64* xt = (const u64*)(sm + B_X2);
#pragma unroll
    for (int i = 0; i < 7; i++) {
        u64 kd[7];
#pragma unroll
        for (int j = 0; j < 7; j++) kd[j] = pk2(kr[i * 7 + j], kr[i * 7 + j]);
        const int rowoff = (ly + i) * P2W + lx;
#pragma unroll
        for (int cp8 = 0; cp8 < 8; cp8++) {
            const u64* xb = xt + (g * 8 + cp8) * P2PIX + rowoff;
            u64 a = acc2[cp8];
            a = ffma2(kd[0], xb[0], a);
            a = ffma2(kd[1], xb[1], a);
            a = ffma2(kd[2], xb[2], a);
            a = ffma2(kd[3], xb[3], a);
            a = ffma2(kd[4], xb[4], a);
            a = ffma2(kd[5], xb[5], a);
            a = ffma2(kd[6], xb[6], a);
            acc2[cp8] = a;
        }
    }

    float* ob = g_x1 + bb * 64 * 9216 + hw;
#pragma unroll
    for (int cp8 = 0; cp8 < 8; cp8++) {
        float lo, hi; upk2(acc2[cp8], lo, hi);
        int c0 = g * 16 + 2 * cp8;
        float v0 = fmaf(lo, sm[B_SI + c0],     sm[B_SHI + c0]);
        float v1 = fmaf(hi, sm[B_SI + c0 + 1], sm[B_SHI + c0 + 1]);
        ob[c0 * 9216]       = gelu_f(v0);
        ob[(c0 + 1) * 9216] = gelu_f(v1);
    }
}

/* ======= K2: tf32 MMA GEMM, 64-px tile, 3 CTAs/SM (round-8 structure) ======= */
/* CTA = 64 px x 128 out; 8 m-warps, warp n64 -> 8 n-tiles, 32 accs.     */
#define S2_W    0            /* u32 128*130 = 16640 */
#define S2_CST  16640        /* 128 */
#define S2_Y    16768        /* [2][16][68] = 2176 */
#define S2_FLOATS 18944
#define S2_BYTES (S2_FLOATS * 4)   /* 75776 B -> 3 CTAs/SM */

__global__ void __launch_bounds__(256, 3)
k2_mma(const float* __restrict__ x,
       const float* __restrict__ w_conv,
       const float* __restrict__ g_c, const float* __restrict__ b_c,
       const float* __restrict__ m_c, const float* __restrict__ v_c,
       const float* __restrict__ w_map, const float* __restrict__ b_map,
       const float* __restrict__ g_m, const float* __restrict__ b_m,
       const float* __restrict__ m_m, const float* __restrict__ v_m,
       float* __restrict__ out)
{
    extern __shared__ float smf[];
    u32* smu = (u32*)smf;
    const int tid = threadIdx.x;

    for (int i = tid; i < 16384; i += 256) {
        int o = i >> 7, k = i & 127;
        float v;
        if (k < 64) v = w_conv[o * 64 + k]        * (g_c[o] * rsqrtf(v_c[o] + EPSF));
        else        v = w_map [o * 64 + (k - 64)] * (g_m[o] * rsqrtf(v_m[o] + EPSF));
        smu[S2_W + o * 130 + k] = tf32c(v);
    }
    if (tid < 128) {
        float sc_c = g_c[tid] * rsqrtf(v_c[tid] + EPSF);
        float sc_m = g_m[tid] * rsqrtf(v_m[tid] + EPSF);
        smf[S2_CST + tid] = (b_c[tid] - m_c[tid] * sc_c)
                          + sc_m * b_map[tid]
                          + (b_m[tid] - m_m[tid] * sc_m);
    }

    const int P0  = blockIdx.x * 64;
    const int b   = P0 / 9216;
    const int off = P0 - b * 9216;

    const int ldr  = tid >> 4;           /* k row 0..15 */
    const int ldc4 = (tid & 15) * 4;     /* px col, step 4 */
    const float* x1base = g_x1 + (b * 64) * 9216 + off;
    const float* xbase  = x    + (b * 64) * 9216 + off;

    /* stage chunk 0 (k = 0..15, from g_x1) */
    float4 v0 = *(const float4*)(x1base + ldr * 9216 + ldc4);
    {
        u32* yd = smu + S2_Y + ldr * 68 + ldc4;
        uint4 s;
        s.x = tf32c(v0.x); s.y = tf32c(v0.y); s.z = tf32c(v0.z); s.w = tf32c(v0.w);
        *(uint4*)yd = s;
    }
    __syncthreads();

    const int lane = tid & 31;
    const int gid  = lane >> 2;
    const int tig  = lane & 3;
    const int m0   = (tid >> 5) * 16;

    float c[8][4];
#pragma unroll
    for (int nt = 0; nt < 8; nt++)
#pragma unroll
        for (int q = 0; q < 4; q++) c[nt][q] = 0.f;

#pragma unroll 1
    for (int ch = 0; ch < 8; ch++) {
        if (ch < 7) {
            int kg = (ch + 1) * 16 + ldr;
            const float* src = (kg < 64) ? (x1base + kg * 9216)
                                         : (xbase + (kg - 64) * 9216);
            v0 = *(const float4*)(src + ldc4);
        }

        const u32* Yb = smu + S2_Y + (ch & 1) * 1088;
#pragma unroll
        for (int ks = 0; ks < 2; ks++) {
            const int kg = ch * 16 + ks * 8;
            u32 a0 = smu[S2_W + (m0 + gid) * 130 + kg + tig];
            u32 a2 = smu[S2_W + (m0 + gid) * 130 + kg + tig + 4];
            u32 a1 = smu[S2_W + (m0 + gid + 8) * 130 + kg + tig];
            u32 a3 = smu[S2_W + (m0 + gid + 8) * 130 + kg + tig + 4];
            const u32* bb0 = Yb + (ks * 8 + tig) * 68 + gid;
            const u32* bb1 = Yb + (ks * 8 + tig + 4) * 68 + gid;
#pragma unroll
            for (int nt = 0; nt < 8; nt++) {
                u32 b0 = bb0[nt * 8];
                u32 b1 = bb1[nt * 8];
                asm volatile(
                    "mma.sync.aligned.m16n8k8.row.col.f32.tf32.tf32.f32 "
                    "{%0,%1,%2,%3}, {%4,%5,%6,%7}, {%8,%9}, {%0,%1,%2,%3};"
                    : "+f"(c[nt][0]), "+f"(c[nt][1]), "+f"(c[nt][2]), "+f"(c[nt][3])
                    : "r"(a0), "r"(a1), "r"(a2), "r"(a3), "r"(b0), "r"(b1));
            }
        }

        if (ch < 7) {
            u32* yd = smu + S2_Y + ((ch + 1) & 1) * 1088 + ldr * 68 + ldc4;
            uint4 s;
            s.x = tf32c(v0.x); s.y = tf32c(v0.y); s.z = tf32c(v0.z); s.w = tf32c(v0.w);
            *(uint4*)yd = s;
        }
        __syncthreads();
    }

    /* epilogue: bias + gelu, STG.64 */
    float* ob = out + (b * 128) * 9216 + off;
    const int o0 = m0 + gid;
    const float cst0 = smf[S2_CST + o0];
    const float cst1 = smf[S2_CST + o0 + 8];
#pragma unroll
    for (int nt = 0; nt < 8; nt++) {
        int pxl = nt * 8 + tig * 2;
        float2 r0, r1;
        r0.x = gelu_f(c[nt][0] + cst0);
        r0.y = gelu_f(c[nt][1] + cst0);
        r1.x = gelu_f(c[nt][2] + cst1);
        r1.y = gelu_f(c[nt][3] + cst1);
        *(float2*)(ob + o0 * 9216 + pxl)       = r0;
        *(float2*)(ob + (o0 + 8) * 9216 + pxl) = r1;
    }
}

extern "C" void kernel_launch(void* const* d_in, const int* in_sizes, int n_in,
                              void* d_out, int out_size)
{
    (void)in_sizes; (void)n_in; (void)out_size;
    const float* x        = (const float*)d_in[0];
    const float* w_reduce = (const float*)d_in[1];
    const float* g_r = (const float*)d_in[2];
    const float* b_r = (const float*)d_in[3];
    const float* m_r = (const float*)d_in[4];
    const float* v_r = (const float*)d_in[5];
    const float* w_span = (const float*)d_in[6];
    const float* b_span = (const float*)d_in[7];
    const float* g_i = (const float*)d_in[8];
    const float* b_i = (const float*)d_in[9];
    const float* m_i = (const float*)d_in[10];
    const float* v_i = (const float*)d_in[11];
    const float* w_conv = (const float*)d_in[12];
    const float* g_c = (const float*)d_in[13];
    const float* b_c = (const float*)d_in[14];
    const float* m_c = (const float*)d_in[15];
    const float* v_c = (const float*)d_in[16];
    const float* w_map = (const float*)d_in[17];
    const float* b_map = (const float*)d_in[18];
    const float* g_m = (const float*)d_in[19];
    const float* b_m = (const float*)d_in[20];
    const float* m_m = (const float*)d_in[21];
    const float* v_m = (const float*)d_in[22];
    float* out = (float*)d_out;

    cudaFuncSetAttribute(k01_kern,       cudaFuncAttributeMaxDynamicSharedMemorySize, J_BYTES);
    cudaFuncSetAttribute(k1b_involution, cudaFuncAttributeMaxDynamicSharedMemorySize, B_BYTES);
    cudaFuncSetAttribute(k2_mma,         cudaFuncAttributeMaxDynamicSharedMemorySize, S2_BYTES);

    k01_kern<<<576, 256, J_BYTES>>>(x, w_reduce, g_r, b_r, m_r, v_r, w_span, b_span);

    dim3 gb(96 / B1W, 96 / B1H, 4);   /* 6 x 24 x 4 = 576 */
    k1b_involution<<<gb, 256, B_BYTES>>>(x, g_i, b_i, m_i, v_i);

    k2_mma<<<576, 256, S2_BYTES>>>(x, w_conv, g_c, b_c, m_c, v_c,
                                   w_map, b_map, g_m, b_m, m_m, v_m, out);
}

// round 14
// speedup vs baseline: 1.1504x; 1.1101x over previous
#include <cuda_runtime.h>
#include <math.h>

#define EPSF 1e-5f

typedef unsigned long long u64;
typedef unsigned int u32;

__device__ __forceinline__ u64 pk2(float a, float b) {
    u64 r;
    asm("mov.b64 %0, {%1, %2};" : "=l"(r) : "r"(__float_as_uint(a)), "r"(__float_as_uint(b)));
    return r;
}
__device__ __forceinline__ u64 ffma2(u64 a, u64 b, u64 c) {
    u64 d;
    asm("fma.rn.f32x2 %0, %1, %2, %3;" : "=l"(d) : "l"(a), "l"(b), "l"(c));
    return d;
}
__device__ __forceinline__ void upk2(u64 v, float& lo, float& hi) {
    unsigned int l, h;
    asm("mov.b64 {%0, %1}, %2;" : "=r"(l), "=r"(h) : "l"(v));
    lo = __uint_as_float(l); hi = __uint_as_float(h);
}
__device__ __forceinline__ float gelu_f(float v) {
    return 0.5f * v * (1.0f + erff(v * 0.70710678118654752f));
}
__device__ __forceinline__ u32 tf32c(float f) {
    u32 r;
    asm("cvt.rna.tf32.f32 %0, %1;" : "=r"(r) : "f"(f));
    return r;
}
__device__ __forceinline__ void cpasync16(u32 saddr, const void* g) {
    asm volatile("cp.async.ca.shared.global [%0], [%1], 16;" :: "r"(saddr), "l"(g));
}

/* intermediates */
__device__ float g_x1[4 * 64 * 9216];    /* gelu(bn(involution)) */
__device__ float g_kern[196 * 36864];    /* per-pixel kernels [g*49+o][pix] */

/* ====== K01: x -> t (direct LDG) -> kern[196][pix]  (round-13 proven) ====== */
#define J_WR    0
#define J_BR    1024
#define J_TPART 1040
#define J_T     5648
#define J_WSP   6800
#define J_BSP   10000
#define J_FLOATS 10200
#define J_BYTES (J_FLOATS * 4)

__global__ void __launch_bounds__(256, 3)
k01_kern(const float* __restrict__ x,
         const float* __restrict__ w_reduce,
         const float* __restrict__ g_r, const float* __restrict__ b_r,
         const float* __restrict__ m_r, const float* __restrict__ v_r,
         const float* __restrict__ w_span, const float* __restrict__ b_span)
{
    extern __shared__ float sm[];
    u64* wsp = (u64*)(sm + J_WSP);
    u64* bsp = (u64*)(sm + J_BSP);
    const int tid = threadIdx.x;

    const int pix0 = blockIdx.x * 64;
    const int b    = pix0 / 9216;
    const int hw0  = pix0 - b * 9216;

    for (int i = tid; i < 1024; i += 256) {
        int c = i >> 4, r = i & 15;
        float sc = g_r[r] * rsqrtf(v_r[r] + EPSF);
        sm[J_WR + c * 16 + r] = w_reduce[r * 64 + c] * sc;
    }
    if (tid < 16) {
        float sc = g_r[tid] * rsqrtf(v_r[tid] + EPSF);
        sm[J_BR + tid] = b_r[tid] - m_r[tid] * sc;
    }
    for (int i = tid; i < 1600; i += 256) {
        int g = i / 400, rem = i - g * 400;
        int op = rem >> 4, r = rem & 15;
        float lo = w_span[(g * 49 + 2 * op) * 16 + r];
        float hi = (2 * op + 1 < 49) ? w_span[(g * 49 + 2 * op + 1) * 16 + r] : 0.f;
        wsp[i] = pk2(lo, hi);
    }
    if (tid < 100) {
        int g = tid / 25, op = tid - g * 25;
        float lo = b_span[g * 49 + 2 * op];
        float hi = (2 * op + 1 < 49) ? b_span[g * 49 + 2 * op + 1] : 0.f;
        bsp[tid] = pk2(lo, hi);
    }
    __syncthreads();

    const int px = tid & 63;
    const int cq = tid >> 6;

    {
        const float* xp = x + b * 64 * 9216 + (cq * 16) * 9216 + hw0 + px;
        u64 t2[8];
#pragma unroll
        for (int q = 0; q < 8; q++) t2[q] = 0ULL;
#pragma unroll
        for (int c = 0; c < 16; c++) {
            float xv = xp[c * 9216];
            u64 xv2 = pk2(xv, xv);
            const ulonglong2* w2 = (const ulonglong2*)(sm + J_WR + (cq * 16 + c) * 16);
#pragma unroll
            for (int q = 0; q < 4; q++) {
                ulonglong2 w = w2[q];
                t2[2 * q + 0] = ffma2(w.x, xv2, t2[2 * q + 0]);
                t2[2 * q + 1] = ffma2(w.y, xv2, t2[2 * q + 1]);
            }
        }
        float* pb = sm + J_TPART + (cq * 64 + px) * 18;
#pragma unroll
        for (int q = 0; q < 8; q++) upk2(t2[q], pb[2 * q], pb[2 * q + 1]);
    }
    __syncthreads();

#pragma unroll
    for (int j = 0; j < 4; j++) {
        int r = cq * 4 + j;
        float s = sm[J_TPART + (0 * 64 + px) * 18 + r]
                + sm[J_TPART + (1 * 64 + px) * 18 + r]
                + sm[J_TPART + (2 * 64 + px) * 18 + r]
                + sm[J_TPART + (3 * 64 + px) * 18 + r];
        s += sm[J_BR + r];
        sm[J_T + px * 18 + r] = fmaxf(s, 0.f);
    }
    __syncthreads();

    const int g = cq;
    u64 t2[16];
    {
        const float* tp = sm + J_T + px * 18;
#pragma unroll
        for (int r = 0; r < 16; r++) { float v = tp[r]; t2[r] = pk2(v, v); }
    }

    float* kout = g_kern + g * 49 * 36864 + pix0 + px;
#pragma unroll 4
    for (int op = 0; op < 25; op++) {
        u64 a = bsp[g * 25 + op];
        const ulonglong2* w2 = (const ulonglong2*)(wsp + (g * 25 + op) * 16);
#pragma unroll
        for (int q = 0; q < 8; q++) {
            ulonglong2 w = w2[q];
            a = ffma2(w.x, t2[2 * q],     a);
            a = ffma2(w.y, t2[2 * q + 1], a);
        }
        float e0, e1; upk2(a, e0, e1);
        kout[(2 * op) * 36864] = e0;
        if (op < 24) kout[(2 * op + 1) * 36864] = e1;
    }
}

/* ============ K1b: involution + BN + gelu (round-11 proven) ============ */
#define B1W 16
#define B1H 4
#define P2W 22
#define P2H 10
#define P2PIX (P2W * P2H)

#define B_X2  0
#define B_SI  14080
#define B_SHI 14144
#define B_FLOATS 14208
#define B_BYTES (B_FLOATS * 4)

__global__ void __launch_bounds__(256, 3)
k1b_involution(const float* __restrict__ x,
               const float* __restrict__ g_i, const float* __restrict__ b_i,
               const float* __restrict__ m_i, const float* __restrict__ v_i)
{
    extern __shared__ float sm[];
    const int tid = threadIdx.x;
    const int bb  = blockIdx.z;
    const int h0  = blockIdx.y * B1H;
    const int w0  = blockIdx.x * B1W;

    {
        const int xbase = bb * 64 * 9216;
        float2* x2 = (float2*)(sm + B_X2);
        for (int i = tid; i < 32 * P2PIX; i += 256) {
            int cp = i / P2PIX;
            int p  = i - cp * P2PIX;
            int r  = p / P2W;
            int cl = p - r * P2W;
            int gh = h0 + r - 3;
            int gw = w0 + cl - 3;
            float v0 = 0.f, v1 = 0.f;
            if ((unsigned)gh < 96u && (unsigned)gw < 96u) {
                int a = xbase + (2 * cp) * 9216 + gh * 96 + gw;
                v0 = x[a];
                v1 = x[a + 9216];
            }
            x2[i] = make_float2(v0, v1);
        }
    }
    if (tid < 64) {
        float sc = g_i[tid] * rsqrtf(v_i[tid] + EPSF);
        sm[B_SI + tid]  = sc;
        sm[B_SHI + tid] = b_i[tid] - m_i[tid] * sc;
    }
    __syncthreads();

    const int px = tid & 63;
    const int g  = tid >> 6;
    const int lx = px & 15;
    const int ly = px >> 4;
    const int hw = (h0 + ly) * 96 + (w0 + lx);
    const int pixg = bb * 9216 + hw;

    float kr[49];
    {
        const float* kp = g_kern + g * 49 * 36864 + pixg;
#pragma unroll
        for (int kk = 0; kk < 49; kk++) kr[kk] = kp[kk * 36864];
    }

    u64 acc2[8];
#pragma unroll
    for (int q = 0; q < 8; q++) acc2[q] = 0ULL;

    const u64* xt = (const u64*)(sm + B_X2);
#pragma unroll
    for (int i = 0; i < 7; i++) {
        u64 kd[7];
#pragma unroll
        for (int j = 0; j < 7; j++) kd[j] = pk2(kr[i * 7 + j], kr[i * 7 + j]);
        const int rowoff = (ly + i) * P2W + lx;
#pragma unroll
        for (int cp8 = 0; cp8 < 8; cp8++) {
            const u64* xb = xt + (g * 8 + cp8) * P2PIX + rowoff;
            u64 a = acc2[cp8];
            a = ffma2(kd[0], xb[0], a);
            a = ffma2(kd[1], xb[1], a);
            a = ffma2(kd[2], xb[2], a);
            a = ffma2(kd[3], xb[3], a);
            a = ffma2(kd[4], xb[4], a);
            a = ffma2(kd[5], xb[5], a);
            a = ffma2(kd[6], xb[6], a);
            acc2[cp8] = a;
        }
    }

    float* ob = g_x1 + bb * 64 * 9216 + hw;
#pragma unroll
    for (int cp8 = 0; cp8 < 8; cp8++) {
        float lo, hi; upk2(acc2[cp8], lo, hi);
        int c0 = g * 16 + 2 * cp8;
        float v0 = fmaf(lo, sm[B_SI + c0],     sm[B_SHI + c0]);
        float v1 = fmaf(hi, sm[B_SI + c0 + 1], sm[B_SHI + c0 + 1]);
        ob[c0 * 9216]       = gelu_f(v0);
        ob[(c0 + 1) * 9216] = gelu_f(v1);
    }
}

/* ==== K2: tf32 MMA GEMM, 128-px tile, cp.async triple-buffered staging ==== */
/* B operand = raw fp32 bits (tf32 truncation); A = rna tf32.              */
#define S2_W    0            /* u32 128*132 = 16896 */
#define S2_CST  16896        /* 128 */
#define S2_Y    17024        /* [3][16][132] = 6336 (raw fp32 bits) */
#define S2_FLOATS 23360
#define S2_BYTES (S2_FLOATS * 4)   /* 93440 B -> 2 CTAs/SM */

__global__ void __launch_bounds__(256, 2)
k2_mma(const float* __restrict__ x,
       const float* __restrict__ w_conv,
       const float* __restrict__ g_c, const float* __restrict__ b_c,
       const float* __restrict__ m_c, const float* __restrict__ v_c,
       const float* __restrict__ w_map, const float* __restrict__ b_map,
       const float* __restrict__ g_m, const float* __restrict__ b_m,
       const float* __restrict__ m_m, const float* __restrict__ v_m,
       float* __restrict__ out)
{
    extern __shared__ float smf[];
    u32* smu = (u32*)smf;
    const int tid = threadIdx.x;

    for (int i = tid; i < 16384; i += 256) {
        int o = i >> 7, k = i & 127;
        float v;
        if (k < 64) v = w_conv[o * 64 + k]        * (g_c[o] * rsqrtf(v_c[o] + EPSF));
        else        v = w_map [o * 64 + (k - 64)] * (g_m[o] * rsqrtf(v_m[o] + EPSF));
        smu[S2_W + o * 132 + k] = tf32c(v);
    }
    if (tid < 128) {
        float sc_c = g_c[tid] * rsqrtf(v_c[tid] + EPSF);
        float sc_m = g_m[tid] * rsqrtf(v_m[tid] + EPSF);
        smf[S2_CST + tid] = (b_c[tid] - m_c[tid] * sc_c)
                          + sc_m * b_map[tid]
                          + (b_m[tid] - m_m[tid] * sc_m);
    }

    const int P0  = blockIdx.x * 128;
    const int b   = P0 / 9216;
    const int off = P0 - b * 9216;

    const int ldr  = tid >> 4;           /* k row 0..15 */
    const int ldc8 = (tid & 15) * 8;     /* px col base */
    const float* x1base = g_x1 + (b * 64) * 9216 + off;
    const float* xbase  = x    + (b * 64) * 9216 + off;

    const u32 ysbase = (u32)__cvta_generic_to_shared(smu + S2_Y);
    const u32 ydst   = ysbase + (u32)(ldr * 132 + ldc8) * 4u;

    /* prologue: chunk 0 -> buf 0 */
    {
        const float* src = x1base + ldr * 9216 + ldc8;
        cpasync16(ydst,       src);
        cpasync16(ydst + 16,  src + 4);
        asm volatile("cp.async.commit_group;" ::: "memory");
    }

    const int lane = tid & 31;
    const int gid  = lane >> 2;
    const int tig  = lane & 3;
    const int m0   = (tid >> 5) * 16;

    float c[16][4];
#pragma unroll
    for (int nt = 0; nt < 16; nt++)
#pragma unroll
        for (int q = 0; q < 4; q++) c[nt][q] = 0.f;

    int buf = 0;
#pragma unroll 1
    for (int ch = 0; ch < 8; ch++) {
        if (ch < 7) {
            int kg = (ch + 1) * 16 + ldr;
            const float* src = (kg < 64) ? (x1base + kg * 9216)
                                         : (xbase + (kg - 64) * 9216);
            int nb = (buf + 1 == 3) ? 0 : buf + 1;
            u32 d = ydst + (u32)(nb * 2112) * 4u;
            cpasync16(d,      src + ldc8);
            cpasync16(d + 16, src + ldc8 + 4);
            asm volatile("cp.async.commit_group;" ::: "memory");
            asm volatile("cp.async.wait_group 1;" ::: "memory");
        } else {
            asm volatile("cp.async.wait_group 0;" ::: "memory");
        }
        __syncthreads();

        const u32* Yb = smu + S2_Y + buf * 2112;
#pragma unroll
        for (int ks = 0; ks < 2; ks++) {
            const int kg = ch * 16 + ks * 8;
            u32 a0 = smu[S2_W + (m0 + gid) * 132 + kg + tig];
            u32 a2 = smu[S2_W + (m0 + gid) * 132 + kg + tig + 4];
            u32 a1 = smu[S2_W + (m0 + gid + 8) * 132 + kg + tig];
            u32 a3 = smu[S2_W + (m0 + gid + 8) * 132 + kg + tig + 4];
            const u32* bb = Yb + (ks * 8 + tig) * 132 + gid;
#pragma unroll
            for (int nt = 0; nt < 16; nt++) {
                u32 b0 = bb[nt * 8];
                u32 b1 = bb[nt * 8 + 4 * 132];
                asm volatile(
                    "mma.sync.aligned.m16n8k8.row.col.f32.tf32.tf32.f32 "
                    "{%0,%1,%2,%3}, {%4,%5,%6,%7}, {%8,%9}, {%0,%1,%2,%3};"
                    : "+f"(c[nt][0]), "+f"(c[nt][1]), "+f"(c[nt][2]), "+f"(c[nt][3])
                    : "r"(a0), "r"(a1), "r"(a2), "r"(a3), "r"(b0), "r"(b1));
            }
        }
        buf = (buf + 1 == 3) ? 0 : buf + 1;
    }

    float* ob = out + (b * 128) * 9216 + off;
    const int o0 = m0 + gid;
    const float cst0 = smf[S2_CST + o0];
    const float cst1 = smf[S2_CST + o0 + 8];
#pragma unroll
    for (int nt = 0; nt < 16; nt++) {
        int pxl = nt * 8 + tig * 2;
        float2 r0, r1;
        r0.x = gelu_f(c[nt][0] + cst0);
        r0.y = gelu_f(c[nt][1] + cst0);
        r1.x = gelu_f(c[nt][2] + cst1);
        r1.y = gelu_f(c[nt][3] + cst1);
        *(float2*)(ob + o0 * 9216 + pxl)       = r0;
        *(float2*)(ob + (o0 + 8) * 9216 + pxl) = r1;
    }
}

extern "C" void kernel_launch(void* const* d_in, const int* in_sizes, int n_in,
                              void* d_out, int out_size)
{
    (void)in_sizes; (void)n_in; (void)out_size;
    const float* x        = (const float*)d_in[0];
    const float* w_reduce = (const float*)d_in[1];
    const float* g_r = (const float*)d_in[2];
    const float* b_r = (const float*)d_in[3];
    const float* m_r = (const float*)d_in[4];
    const float* v_r = (const float*)d_in[5];
    const float* w_span = (const float*)d_in[6];
    const float* b_span = (const float*)d_in[7];
    const float* g_i = (const float*)d_in[8];
    const float* b_i = (const float*)d_in[9];
    const float* m_i = (const float*)d_in[10];
    const float* v_i = (const float*)d_in[11];
    const float* w_conv = (const float*)d_in[12];
    const float* g_c = (const float*)d_in[13];
    const float* b_c = (const float*)d_in[14];
    const float* m_c = (const float*)d_in[15];
    const float* v_c = (const float*)d_in[16];
    const float* w_map = (const float*)d_in[17];
    const float* b_map = (const float*)d_in[18];
    const float* g_m = (const float*)d_in[19];
    const float* b_m = (const float*)d_in[20];
    const float* m_m = (const float*)d_in[21];
    const float* v_m = (const float*)d_in[22];
    float* out = (float*)d_out;

    cudaFuncSetAttribute(k01_kern,       cudaFuncAttributeMaxDynamicSharedMemorySize, J_BYTES);
    cudaFuncSetAttribute(k1b_involution, cudaFuncAttributeMaxDynamicSharedMemorySize, B_BYTES);
    cudaFuncSetAttribute(k2_mma,         cudaFuncAttributeMaxDynamicSharedMemorySize, S2_BYTES);

    k01_kern<<<576, 256, J_BYTES>>>(x, w_reduce, g_r, b_r, m_r, v_r, w_span, b_span);

    dim3 gb(96 / B1W, 96 / B1H, 4);
    k1b_involution<<<gb, 256, B_BYTES>>>(x, g_i, b_i, m_i, v_i);

    k2_mma<<<288, 256, S2_BYTES>>>(x, w_conv, g_c, b_c, m_c, v_c,
                                   w_map, b_map, g_m, b_m, m_m, v_m, out);
}

// round 17
// speedup vs baseline: 1.3071x; 1.1362x over previous
#include <cuda_runtime.h>
#include <cuda_fp16.h>
#include <math.h>

#define EPSF 1e-5f

typedef unsigned long long u64;
typedef unsigned int u32;

__device__ __forceinline__ u64 pk2(float a, float b) {
    u64 r;
    asm("mov.b64 %0, {%1, %2};" : "=l"(r) : "r"(__float_as_uint(a)), "r"(__float_as_uint(b)));
    return r;
}
__device__ __forceinline__ u64 ffma2(u64 a, u64 b, u64 c) {
    u64 d;
    asm("fma.rn.f32x2 %0, %1, %2, %3;" : "=l"(d) : "l"(a), "l"(b), "l"(c));
    return d;
}
__device__ __forceinline__ void upk2(u64 v, float& lo, float& hi) {
    unsigned int l, h;
    asm("mov.b64 {%0, %1}, %2;" : "=r"(l), "=r"(h) : "l"(v));
    lo = __uint_as_float(l); hi = __uint_as_float(h);
}
__device__ __forceinline__ float gelu_f(float v) {
    return 0.5f * v * (1.0f + erff(v * 0.70710678118654752f));
}
/* pack two f32 -> f16x2 (lo in low half) */
__device__ __forceinline__ u32 h2(float lo, float hi) {
    u32 r;
    asm("cvt.rn.f16x2.f32 %0, %1, %2;" : "=r"(r) : "f"(hi), "f"(lo));
    return r;
}
__device__ __forceinline__ void cpasync16(u32 saddr, const void* g) {
    asm volatile("cp.async.ca.shared.global [%0], [%1], 16;" :: "r"(saddr), "l"(g));
}

/* intermediates */
__device__ u32  g_y[64 * 36864];        /* half2 channel pairs: kp<32 = x1, kp>=32 = x */
__device__ float g_kern[196 * 36864];   /* per-pixel kernels [g*49+o][pix] */

/* ====== K01: x -> t (direct LDG) -> kern[196][pix] ====== */
#define J_WR    0
#define J_BR    1024
#define J_TPART 1040
#define J_T     5648
#define J_WSP   6800
#define J_BSP   10000
#define J_FLOATS 10200
#define J_BYTES (J_FLOATS * 4)

__global__ void __launch_bounds__(256, 3)
k01_kern(const float* __restrict__ x,
         const float* __restrict__ w_reduce,
         const float* __restrict__ g_r, const float* __restrict__ b_r,
         const float* __restrict__ m_r, const float* __restrict__ v_r,
         const float* __restrict__ w_span, const float* __restrict__ b_span)
{
    extern __shared__ float sm[];
    u64* wsp = (u64*)(sm + J_WSP);
    u64* bsp = (u64*)(sm + J_BSP);
    const int tid = threadIdx.x;

    const int pix0 = blockIdx.x * 64;
    const int b    = pix0 / 9216;
    const int hw0  = pix0 - b * 9216;

    for (int i = tid; i < 1024; i += 256) {
        int c = i >> 4, r = i & 15;
        float sc = g_r[r] * rsqrtf(v_r[r] + EPSF);
        sm[J_WR + c * 16 + r] = w_reduce[r * 64 + c] * sc;
    }
    if (tid < 16) {
        float sc = g_r[tid] * rsqrtf(v_r[tid] + EPSF);
        sm[J_BR + tid] = b_r[tid] - m_r[tid] * sc;
    }
    for (int i = tid; i < 1600; i += 256) {
        int g = i / 400, rem = i - g * 400;
        int op = rem >> 4, r = rem & 15;
        float lo = w_span[(g * 49 + 2 * op) * 16 + r];
        float hi = (2 * op + 1 < 49) ? w_span[(g * 49 + 2 * op + 1) * 16 + r] : 0.f;
        wsp[i] = pk2(lo, hi);
    }
    if (tid < 100) {
        int g = tid / 25, op = tid - g * 25;
        float lo = b_span[g * 49 + 2 * op];
        float hi = (2 * op + 1 < 49) ? b_span[g * 49 + 2 * op + 1] : 0.f;
        bsp[tid] = pk2(lo, hi);
    }
    __syncthreads();

    const int px = tid & 63;
    const int cq = tid >> 6;

    {
        const float* xp = x + b * 64 * 9216 + (cq * 16) * 9216 + hw0 + px;
        u64 t2[8];
#pragma unroll
        for (int q = 0; q < 8; q++) t2[q] = 0ULL;
#pragma unroll
        for (int c = 0; c < 16; c++) {
            float xv = xp[c * 9216];
            u64 xv2 = pk2(xv, xv);
            const ulonglong2* w2 = (const ulonglong2*)(sm + J_WR + (cq * 16 + c) * 16);
#pragma unroll
            for (int q = 0; q < 4; q++) {
                ulonglong2 w = w2[q];
                t2[2 * q + 0] = ffma2(w.x, xv2, t2[2 * q + 0]);
                t2[2 * q + 1] = ffma2(w.y, xv2, t2[2 * q + 1]);
            }
        }
        float* pb = sm + J_TPART + (cq * 64 + px) * 18;
#pragma unroll
        for (int q = 0; q < 8; q++) upk2(t2[q], pb[2 * q], pb[2 * q + 1]);
    }
    __syncthreads();

#pragma unroll
    for (int j = 0; j < 4; j++) {
        int r = cq * 4 + j;
        float s = sm[J_TPART + (0 * 64 + px) * 18 + r]
                + sm[J_TPART + (1 * 64 + px) * 18 + r]
                + sm[J_TPART + (2 * 64 + px) * 18 + r]
                + sm[J_TPART + (3 * 64 + px) * 18 + r];
        s += sm[J_BR + r];
        sm[J_T + px * 18 + r] = fmaxf(s, 0.f);
    }
    __syncthreads();

    const int g = cq;
    u64 t2[16];
    {
        const float* tp = sm + J_T + px * 18;
#pragma unroll
        for (int r = 0; r < 16; r++) { float v = tp[r]; t2[r] = pk2(v, v); }
    }

    float* kout = g_kern + g * 49 * 36864 + pix0 + px;
#pragma unroll 4
    for (int op = 0; op < 25; op++) {
        u64 aa = bsp[g * 25 + op];      /* two 8-deep chains instead of one 16-deep */
        u64 ab = 0ULL;
        const ulonglong2* w2 = (const ulonglong2*)(wsp + (g * 25 + op) * 16);
#pragma unroll
        for (int q = 0; q < 4; q++) {
            ulonglong2 w = w2[q];
            aa = ffma2(w.x, t2[2 * q],     aa);
            ab = ffma2(w.y, t2[2 * q + 1], ab);
        }
#pragma unroll
        for (int q = 4; q < 8; q++) {
            ulonglong2 w = w2[q];
            aa = ffma2(w.x, t2[2 * q],     aa);
            ab = ffma2(w.y, t2[2 * q + 1], ab);
        }
        float a0, a1, b0, b1;
        upk2(aa, a0, a1); upk2(ab, b0, b1);
        kout[(2 * op) * 36864] = a0 + b0;
        if (op < 24) kout[(2 * op + 1) * 36864] = a1 + b1;
    }
}

/* ==== K1b: involution + BN + gelu -> g_y (half2 pairs, x1 + x copy) ==== */
#define B1W 16
#define B1H 4
#define P2W 22
#define P2H 10
#define P2PIX (P2W * P2H)

#define B_X2  0
#define B_SI  14080
#define B_SHI 14144
#define B_FLOATS 14208
#define B_BYTES (B_FLOATS * 4)

__global__ void __launch_bounds__(256, 3)
k1b_involution(const float* __restrict__ x,
               const float* __restrict__ g_i, const float* __restrict__ b_i,
               const float* __restrict__ m_i, const float* __restrict__ v_i)
{
    extern __shared__ float sm[];
    const int tid = threadIdx.x;
    const int bb  = blockIdx.z;
    const int h0  = blockIdx.y * B1H;
    const int w0  = blockIdx.x * B1W;

    {
        const int xbase = bb * 64 * 9216;
        float2* x2 = (float2*)(sm + B_X2);
        for (int i = tid; i < 32 * P2PIX; i += 256) {
            int cp = i / P2PIX;
            int p  = i - cp * P2PIX;
            int r  = p / P2W;
            int cl = p - r * P2W;
            int gh = h0 + r - 3;
            int gw = w0 + cl - 3;
            float v0 = 0.f, v1 = 0.f;
            if ((unsigned)gh < 96u && (unsigned)gw < 96u) {
                int a = xbase + (2 * cp) * 9216 + gh * 96 + gw;
                v0 = x[a];
                v1 = x[a + 9216];
            }
            x2[i] = make_float2(v0, v1);
        }
    }
    if (tid < 64) {
        float sc = g_i[tid] * rsqrtf(v_i[tid] + EPSF);
        sm[B_SI + tid]  = sc;
        sm[B_SHI + tid] = b_i[tid] - m_i[tid] * sc;
    }
    __syncthreads();

    const int px = tid & 63;
    const int g  = tid >> 6;
    const int lx = px & 15;
    const int ly = px >> 4;
    const int hw = (h0 + ly) * 96 + (w0 + lx);
    const int pixg = bb * 9216 + hw;

    float kr[49];
    {
        const float* kp = g_kern + g * 49 * 36864 + pixg;
#pragma unroll
        for (int kk = 0; kk < 49; kk++) kr[kk] = kp[kk * 36864];
    }

    u64 acc2[8];
#pragma unroll
    for (int q = 0; q < 8; q++) acc2[q] = 0ULL;

    const u64* xt = (const u64*)(sm + B_X2);
#pragma unroll
    for (int i = 0; i < 7; i++) {
        u64 kd[7];
#pragma unroll
        for (int j = 0; j < 7; j++) kd[j] = pk2(kr[i * 7 + j], kr[i * 7 + j]);
        const int rowoff = (ly + i) * P2W + lx;
#pragma unroll
        for (int cp8 = 0; cp8 < 8; cp8++) {
            const u64* xb = xt + (g * 8 + cp8) * P2PIX + rowoff;
            u64 a = acc2[cp8];
            a = ffma2(kd[0], xb[0], a);
            a = ffma2(kd[1], xb[1], a);
            a = ffma2(kd[2], xb[2], a);
            a = ffma2(kd[3], xb[3], a);
            a = ffma2(kd[4], xb[4], a);
            a = ffma2(kd[5], xb[5], a);
            a = ffma2(kd[6], xb[6], a);
            acc2[cp8] = a;
        }
    }

    /* write x1 pairs (kp = g*8+cp8) and x center pairs (kp = 32+g*8+cp8) as half2 */
    const int cen = (ly + 3) * P2W + (lx + 3);
    const float2* x2c = (const float2*)(sm + B_X2);
    u32* yo1 = g_y + (g * 8) * 36864 + pixg;
    u32* yox = g_y + (32 + g * 8) * 36864 + pixg;
#pragma unroll
    for (int cp8 = 0; cp8 < 8; cp8++) {
        float lo, hi; upk2(acc2[cp8], lo, hi);
        int c0 = g * 16 + 2 * cp8;
        float v0 = gelu_f(fmaf(lo, sm[B_SI + c0],     sm[B_SHI + c0]));
        float v1 = gelu_f(fmaf(hi, sm[B_SI + c0 + 1], sm[B_SHI + c0 + 1]));
        yo1[cp8 * 36864] = h2(v0, v1);
        float2 xc = x2c[(g * 8 + cp8) * P2PIX + cen];
        yox[cp8 * 36864] = h2(xc.x, xc.y);
    }
}

/* ==== K2: fp16 m16n8k16 MMA GEMM, cp.async triple-buffered ==== */
/* out[o=128][pix] = W[o][k=128] . Y[k][pix]; Y/W in half2 k-pairs.   */
#define Y_STR 136                     /* u32 row stride (8 banks offset / row) */
#define S2_W    0                     /* u32 [o=128][kp pad 68] = 8704 */
#define S2_CST  8704                  /* 128 floats */
#define S2_Y    8832                  /* u32 [3][8][136] = 3264 */
#define S2_FLOATS 12096
#define S2_BYTES (S2_FLOATS * 4)      /* 48384 B */

__global__ void __launch_bounds__(256, 2)
k2_mma(const float* __restrict__ w_conv,
       const float* __restrict__ g_c, const float* __restrict__ b_c,
       const float* __restrict__ m_c, const float* __restrict__ v_c,
       const float* __restrict__ w_map, const float* __restrict__ b_map,
       const float* __restrict__ g_m, const float* __restrict__ b_m,
       const float* __restrict__ m_m, const float* __restrict__ v_m,
       float* __restrict__ out)
{
    extern __shared__ float smf[];
    u32* smu = (u32*)smf;
    const int tid = threadIdx.x;

    /* fold BN into W, pack half2 k-pairs: Wp[o][kp] = {w(o,2kp), w(o,2kp+1)} */
    for (int i = tid; i < 128 * 64; i += 256) {
        int o = i >> 6, kp = i & 63;
        float sc_c = g_c[o] * rsqrtf(v_c[o] + EPSF);
        float sc_m = g_m[o] * rsqrtf(v_m[o] + EPSF);
        int k0 = 2 * kp, k1 = 2 * kp + 1;
        float lo = (k0 < 64) ? w_conv[o * 64 + k0] * sc_c : w_map[o * 64 + (k0 - 64)] * sc_m;
        float hi = (k1 < 64) ? w_conv[o * 64 + k1] * sc_c : w_map[o * 64 + (k1 - 64)] * sc_m;
        smu[S2_W + o * 68 + kp] = h2(lo, hi);
    }
    if (tid < 128) {
        float sc_c = g_c[tid] * rsqrtf(v_c[tid] + EPSF);
        float sc_m = g_m[tid] * rsqrtf(v_m[tid] + EPSF);
        smf[S2_CST + tid] = (b_c[tid] - m_c[tid] * sc_c)
                          + sc_m * b_map[tid]
                          + (b_m[tid] - m_m[tid] * sc_m);
    }

    const int P0 = blockIdx.x * 128;

    const int ldr  = tid >> 5;           /* kp row in chunk, 0..7 */
    const int ldc4 = (tid & 31) * 4;     /* px col base */
    const u32* ybase = g_y + P0 + ldc4;

    const u32 ysbase = (u32)__cvta_generic_to_shared(smu + S2_Y);
    const u32 ydst   = ysbase + (u32)(ldr * Y_STR + ldc4) * 4u;

    /* prologue: chunk 0 (kp rows 0..7) -> buf 0 */
    cpasync16(ydst, ybase + ldr * 36864);
    asm volatile("cp.async.commit_group;" ::: "memory");

    const int lane = tid & 31;
    const int gid  = lane >> 2;
    const int tig  = lane & 3;
    const int m0   = (tid >> 5) * 16;

    float c[16][4];
#pragma unroll
    for (int nt = 0; nt < 16; nt++)
#pragma unroll
        for (int q = 0; q < 4; q++) c[nt][q] = 0.f;

    int buf = 0;
#pragma unroll 1
    for (int ch = 0; ch < 8; ch++) {
        if (ch < 7) {
            int nb = (buf + 1 == 3) ? 0 : buf + 1;
            u32 d = ydst + (u32)(nb * 8 * Y_STR) * 4u;
            cpasync16(d, ybase + ((ch + 1) * 8 + ldr) * 36864);
            asm volatile("cp.async.commit_group;" ::: "memory");
            asm volatile("cp.async.wait_group 1;" ::: "memory");
        } else {
            asm volatile("cp.async.wait_group 0;" ::: "memory");
        }
        __syncthreads();

        const u32* Yb = smu + S2_Y + buf * 8 * Y_STR;
        u32 a0 = smu[S2_W + (m0 + gid) * 68 + ch * 8 + tig];
        u32 a2 = smu[S2_W + (m0 + gid) * 68 + ch * 8 + tig + 4];
        u32 a1 = smu[S2_W + (m0 + gid + 8) * 68 + ch * 8 + tig];
        u32 a3 = smu[S2_W + (m0 + gid + 8) * 68 + ch * 8 + tig + 4];
        const u32* bb0 = Yb + tig * Y_STR + gid;
        const u32* bb1 = Yb + (tig + 4) * Y_STR + gid;
#pragma unroll
        for (int nt = 0; nt < 16; nt++) {
            u32 b0 = bb0[nt * 8];
            u32 b1 = bb1[nt * 8];
            asm volatile(
                "mma.sync.aligned.m16n8k16.row.col.f32.f16.f16.f32 "
                "{%0,%1,%2,%3}, {%4,%5,%6,%7}, {%8,%9}, {%0,%1,%2,%3};"
                : "+f"(c[nt][0]), "+f"(c[nt][1]), "+f"(c[nt][2]), "+f"(c[nt][3])
                : "r"(a0), "r"(a1), "r"(a2), "r"(a3), "r"(b0), "r"(b1));
        }
        buf = (buf + 1 == 3) ? 0 : buf + 1;
    }

    const int b   = P0 / 9216;
    const int off = P0 - b * 9216;
    float* ob = out + (b * 128) * 9216 + off;
    const int o0 = m0 + gid;
    const float cst0 = smf[S2_CST + o0];
    const float cst1 = smf[S2_CST + o0 + 8];
#pragma unroll
    for (int nt = 0; nt < 16; nt++) {
        int pxl = nt * 8 + tig * 2;
        float2 r0, r1;
        r0.x = gelu_f(c[nt][0] + cst0);
        r0.y = gelu_f(c[nt][1] + cst0);
        r1.x = gelu_f(c[nt][2] + cst1);
        r1.y = gelu_f(c[nt][3] + cst1);
        *(float2*)(ob + o0 * 9216 + pxl)       = r0;
        *(float2*)(ob + (o0 + 8) * 9216 + pxl) = r1;
    }
}

extern "C" void kernel_launch(void* const* d_in, const int* in_sizes, int n_in,
                              void* d_out, int out_size)
{
    (void)in_sizes; (void)n_in; (void)out_size;
    const float* x        = (const float*)d_in[0];
    const float* w_reduce = (const float*)d_in[1];
    const float* g_r = (const float*)d_in[2];
    const float* b_r = (const float*)d_in[3];
    const float* m_r = (const float*)d_in[4];
    const float* v_r = (const float*)d_in[5];
    const float* w_span = (const float*)d_in[6];
    const float* b_span = (const float*)d_in[7];
    const float* g_i = (const float*)d_in[8];
    const float* b_i = (const float*)d_in[9];
    const float* m_i = (const float*)d_in[10];
    const float* v_i = (const float*)d_in[11];
    const float* w_conv = (const float*)d_in[12];
    const float* g_c = (const float*)d_in[13];
    const float* b_c = (const float*)d_in[14];
    const float* m_c = (const float*)d_in[15];
    const float* v_c = (const float*)d_in[16];
    const float* w_map = (const float*)d_in[17];
    const float* b_map = (const float*)d_in[18];
    const float* g_m = (const float*)d_in[19];
    const float* b_m = (const float*)d_in[20];
    const float* m_m = (const float*)d_in[21];
    const float* v_m = (const float*)d_in[22];
    float* out = (float*)d_out;

    cudaFuncSetAttribute(k01_kern,       cudaFuncAttributeMaxDynamicSharedMemorySize, J_BYTES);
    cudaFuncSetAttribute(k1b_involution, cudaFuncAttributeMaxDynamicSharedMemorySize, B_BYTES);
    cudaFuncSetAttribute(k2_mma,         cudaFuncAttributeMaxDynamicSharedMemorySize, S2_BYTES);

    k01_kern<<<576, 256, J_BYTES>>>(x, w_reduce, g_r, b_r, m_r, v_r, w_span, b_span);

    dim3 gb(96 / B1W, 96 / B1H, 4);
    k1b_involution<<<gb, 256, B_BYTES>>>(x, g_i, b_i, m_i, v_i);

    k2_mma<<<288, 256, S2_BYTES>>>(w_conv, g_c, b_c, m_c, v_c,
                                   w_map, b_map, g_m, b_m, m_m, v_m, out);
}